// round 10
// baseline (speedup 1.0000x reference)
#include <cuda_runtime.h>
#include <cuda_bf16.h>

// ModernBertCanonLayer: varlen depthwise conv (K=5) + bias + residual.
// Round-7 kernel: unroll-6 token groups (MLP=6 independent prefetch LDG.128),
// RPT=54 = exactly 9 groups (no scalar tail), interior fast path.

#define CCH   768
#define C4    (CCH / 4)      // 192 float4 per row
#define RPT   54             // tokens per y-stream = 9 * 6 (no tail)
#define YR    2              // y-streams per block

#define ZERO4 make_float4(0.f, 0.f, 0.f, 0.f)

#define FMA4(acc, wk, r)                                   \
    acc.x = fmaf((wk)[0], (r).x, acc.x);                   \
    acc.y = fmaf((wk)[1], (r).y, acc.y);                   \
    acc.z = fmaf((wk)[2], (r).z, acc.z);                   \
    acc.w = fmaf((wk)[3], (r).w, acc.w);

#define FMA4M(acc, wk, r, m)                               \
    acc.x = fmaf((m) ? (wk)[0] : 0.f, (r).x, acc.x);       \
    acc.y = fmaf((m) ? (wk)[1] : 0.f, (r).y, acc.y);       \
    acc.z = fmaf((m) ? (wk)[2] : 0.f, (r).z, acc.z);       \
    acc.w = fmaf((m) ? (wk)[3] : 0.f, (r).w, acc.w);

// Fast token (all taps in-segment): rows A0..A4, center A2.
#define TOKEN_FAST(it, A0, A1, A2, A3, A4)                 \
    do {                                                   \
        float4 acc = b4;                                   \
        FMA4(acc, w[0], A0); FMA4(acc, w[1], A1);          \
        FMA4(acc, w[2], A2); FMA4(acc, w[3], A3);          \
        FMA4(acc, w[4], A4);                               \
        float4 o;                                          \
        o.x = (A2).x + acc.x; o.y = (A2).y + acc.y;        \
        o.z = (A2).z + acc.z; o.w = (A2).w + acc.w;        \
        __stcs(&o4[(size_t)(it) * C4 + c4], o);            \
    } while (0)

// Slow token: advances segment window and applies per-tap masks.
#define TOKEN_SLOW(it, A0, A1, A2, A3, A4)                 \
    do {                                                   \
        while ((it) >= hhi) { ++ss; llo = s_cu[ss]; hhi = s_cu[ss + 1]; } \
        float4 acc = b4;                                   \
        FMA4M(acc, w[0], A0, (it) - 2 >= llo);             \
        FMA4M(acc, w[1], A1, (it) - 1 >= llo);             \
        FMA4(acc, w[2], A2);                               \
        FMA4M(acc, w[3], A3, (it) + 1 < hhi);              \
        FMA4M(acc, w[4], A4, (it) + 2 < hhi);              \
        float4 o;                                          \
        o.x = (A2).x + acc.x; o.y = (A2).y + acc.y;        \
        o.z = (A2).z + acc.z; o.w = (A2).w + acc.w;        \
        __stcs(&o4[(size_t)(it) * C4 + c4], o);            \
    } while (0)

__global__ __launch_bounds__(C4 * YR, 2)
void canon_kernel(const float* __restrict__ x,
                  const int*   __restrict__ cu, int ncu,
                  const float* __restrict__ weight,
                  const float* __restrict__ bias,
                  float*       __restrict__ out,
                  int T)
{
    __shared__ int s_cu[64];
    {
        int tid = threadIdx.y * blockDim.x + threadIdx.x;
        if (tid < ncu) s_cu[tid] = cu[tid];
    }
    __syncthreads();

    const int c4   = threadIdx.x;                               // 0..191
    const int base = (blockIdx.x * YR + threadIdx.y) * RPT;
    if (base >= T) return;

    float w[5][4];
    {
        const int c0 = c4 * 4;
        #pragma unroll
        for (int j = 0; j < 4; ++j)
            #pragma unroll
            for (int k = 0; k < 5; ++k)
                w[k][j] = weight[(c0 + j) * 5 + k];
    }
    const float4 b4 = reinterpret_cast<const float4*>(bias)[c4];

    const float4* __restrict__ x4 = reinterpret_cast<const float4*>(x);
    float4* __restrict__       o4 = reinterpret_cast<float4*>(out);

    // Segment of token `base` (searchsorted-right; handles empty sequences).
    int s = 0;
    while (base >= s_cu[s + 1]) ++s;
    int lo = s_cu[s], hi = s_cu[s + 1];

    // Window registers: rows base-2 .. base+2.
    float4 r0, r1, r2, r3, r4;
    {
        int j;
        j = base - 2; r0 = (j >= 0) ? x4[(size_t)j * C4 + c4] : ZERO4;
        j = base - 1; r1 = (j >= 0) ? x4[(size_t)j * C4 + c4] : ZERO4;
        r2 = x4[(size_t)base * C4 + c4];
        j = base + 1; r3 = (j < T) ? x4[(size_t)j * C4 + c4] : ZERO4;
        j = base + 2; r4 = (j < T) ? x4[(size_t)j * C4 + c4] : ZERO4;
    }

    const int iend = (base + RPT < T) ? (base + RPT) : T;
    int i = base;

    // ---- unroll-6 main loop: 6 independent prefetch loads per group ----
    for (; i + 5 < iend; i += 6) {
        // Prefetch rows i+3 .. i+8 (independent -> MLP=6).
        const int j0 = i + 3;
        float4 n0 = (j0     < T) ? x4[(size_t)(j0    ) * C4 + c4] : ZERO4;
        float4 n1 = (j0 + 1 < T) ? x4[(size_t)(j0 + 1) * C4 + c4] : ZERO4;
        float4 n2 = (j0 + 2 < T) ? x4[(size_t)(j0 + 2) * C4 + c4] : ZERO4;
        float4 n3 = (j0 + 3 < T) ? x4[(size_t)(j0 + 3) * C4 + c4] : ZERO4;
        float4 n4 = (j0 + 4 < T) ? x4[(size_t)(j0 + 4) * C4 + c4] : ZERO4;
        float4 n5 = (j0 + 5 < T) ? x4[(size_t)(j0 + 5) * C4 + c4] : ZERO4;

        // Catch segment window up to token i (warp-uniform).
        while (i >= hi) { ++s; lo = s_cu[s]; hi = s_cu[s + 1]; }

        if (i - 2 >= lo && i + 7 < hi) {
            // Interior fast path: tokens i..i+5 have all taps in-segment.
            TOKEN_FAST(i    , r0, r1, r2, r3, r4);
            TOKEN_FAST(i + 1, r1, r2, r3, r4, n0);
            TOKEN_FAST(i + 2, r2, r3, r4, n0, n1);
            TOKEN_FAST(i + 3, r3, r4, n0, n1, n2);
            TOKEN_FAST(i + 4, r4, n0, n1, n2, n3);
            TOKEN_FAST(i + 5, n0, n1, n2, n3, n4);
        } else {
            int ss = s, llo = lo, hhi = hi;
            TOKEN_SLOW(i    , r0, r1, r2, r3, r4);
            TOKEN_SLOW(i + 1, r1, r2, r3, r4, n0);
            TOKEN_SLOW(i + 2, r2, r3, r4, n0, n1);
            TOKEN_SLOW(i + 3, r3, r4, n0, n1, n2);
            TOKEN_SLOW(i + 4, r4, n0, n1, n2, n3);
            TOKEN_SLOW(i + 5, n0, n1, n2, n3, n4);
        }

        // Shift window to rows (i+6)-2 .. (i+6)+2 = i+4 .. i+8.
        r0 = n1; r1 = n2; r2 = n3; r3 = n4; r4 = n5;
    }

    // ---- scalar tail (only for the final partial block) ----
    for (; i < iend; ++i) {
        while (i >= hi) { ++s; lo = s_cu[s]; hi = s_cu[s + 1]; }
        int ss = s, llo = lo, hhi = hi;
        TOKEN_SLOW(i, r0, r1, r2, r3, r4);
        int jn = i + 3;
        float4 nn = (jn < T) ? x4[(size_t)jn * C4 + c4] : ZERO4;
        r0 = r1; r1 = r2; r2 = r3; r3 = r4; r4 = nn;
    }
}

extern "C" void kernel_launch(void* const* d_in, const int* in_sizes, int n_in,
                              void* d_out, int out_size)
{
    const float* x      = (const float*)d_in[0];
    const int*   cu     = (const int*)  d_in[1];
    const float* weight = (const float*)d_in[2];
    const float* bias   = (const float*)d_in[3];
    float*       out    = (float*)d_out;

    const int T   = in_sizes[0] / CCH;
    const int ncu = in_sizes[1];

    const int tokens_per_block = YR * RPT;                      // 108
    const int grid = (T + tokens_per_block - 1) / tokens_per_block;  // 607
    dim3 block(C4, YR);                                         // (192, 2) = 384 threads
    canon_kernel<<<grid, block>>>(x, cu, ncu, weight, bias, out, T);
}

// round 11
// speedup vs baseline: 1.0154x; 1.0154x over previous
#include <cuda_runtime.h>
#include <cuda_bf16.h>

// ModernBertCanonLayer: varlen depthwise conv (K=5) + bias + residual.
// Round-10: exact 2-wave grid (592 CTAs = 2 x 296 resident), balanced 55/56
// token streams, unroll-4 (MLP=4 — measured sufficient), clamped halo loads
// (masks provide correctness), pointer-walking addressing.

#define CCH   768
#define C4    (CCH / 4)      // 192 float4 per row
#define YR    2              // token streams per block
#define GRID  592            // 2 exact waves of 296 resident CTAs
#define NSTREAMS (GRID * YR) // 1184

#define FMA4(acc, wk, r)                                   \
    acc.x = fmaf((wk)[0], (r).x, acc.x);                   \
    acc.y = fmaf((wk)[1], (r).y, acc.y);                   \
    acc.z = fmaf((wk)[2], (r).z, acc.z);                   \
    acc.w = fmaf((wk)[3], (r).w, acc.w);

#define FMA4M(acc, wk, r, m)                               \
    acc.x = fmaf((m) ? (wk)[0] : 0.f, (r).x, acc.x);       \
    acc.y = fmaf((m) ? (wk)[1] : 0.f, (r).y, acc.y);       \
    acc.z = fmaf((m) ? (wk)[2] : 0.f, (r).z, acc.z);       \
    acc.w = fmaf((m) ? (wk)[3] : 0.f, (r).w, acc.w);

// Fast token (all taps in-segment): rows A0..A4, center A2.
#define TOKEN_FAST(po, A0, A1, A2, A3, A4)                 \
    do {                                                   \
        float4 acc = b4;                                   \
        FMA4(acc, w[0], A0); FMA4(acc, w[1], A1);          \
        FMA4(acc, w[2], A2); FMA4(acc, w[3], A3);          \
        FMA4(acc, w[4], A4);                               \
        float4 o;                                          \
        o.x = (A2).x + acc.x; o.y = (A2).y + acc.y;        \
        o.z = (A2).z + acc.z; o.w = (A2).w + acc.w;        \
        __stcs((po), o);                                   \
    } while (0)

// Slow token: advances segment window and applies per-tap masks.
// Garbage (clamped) rows are always masked out here.
#define TOKEN_SLOW(it, po, A0, A1, A2, A3, A4)             \
    do {                                                   \
        while ((it) >= hhi) { ++ss; llo = s_cu[ss]; hhi = s_cu[ss + 1]; } \
        float4 acc = b4;                                   \
        FMA4M(acc, w[0], A0, (it) - 2 >= llo);             \
        FMA4M(acc, w[1], A1, (it) - 1 >= llo);             \
        FMA4(acc, w[2], A2);                               \
        FMA4M(acc, w[3], A3, (it) + 1 < hhi);              \
        FMA4M(acc, w[4], A4, (it) + 2 < hhi);              \
        float4 o;                                          \
        o.x = (A2).x + acc.x; o.y = (A2).y + acc.y;        \
        o.z = (A2).z + acc.z; o.w = (A2).w + acc.w;        \
        __stcs((po), o);                                   \
    } while (0)

__global__ __launch_bounds__(C4 * YR, 2)
void canon_kernel(const float* __restrict__ x,
                  const int*   __restrict__ cu, int ncu,
                  const float* __restrict__ weight,
                  const float* __restrict__ bias,
                  float*       __restrict__ out,
                  int T)
{
    __shared__ int s_cu[64];
    {
        int tid = threadIdx.y * blockDim.x + threadIdx.x;
        if (tid < ncu) s_cu[tid] = cu[tid];
    }
    __syncthreads();

    const int c4 = threadIdx.x;                              // 0..191
    const int S  = blockIdx.x * YR + threadIdx.y;            // stream id 0..1183

    // Balanced split: first R streams get Lbig tokens, rest Lbig-1.
    const int Lsmall = T / NSTREAMS;                         // 55
    const int R      = T - Lsmall * NSTREAMS;                // 416
    const int len    = Lsmall + (S < R ? 1 : 0);
    const int base   = S * Lsmall + (S < R ? S : R);
    if (len <= 0) return;

    float w[5][4];
    {
        const int c0 = c4 * 4;
        #pragma unroll
        for (int j = 0; j < 4; ++j)
            #pragma unroll
            for (int k = 0; k < 5; ++k)
                w[k][j] = weight[(c0 + j) * 5 + k];
    }
    const float4 b4 = reinterpret_cast<const float4*>(bias)[c4];

    const float4* __restrict__ x4 = reinterpret_cast<const float4*>(x);
    float4* __restrict__       o4 = reinterpret_cast<float4*>(out);

    // Segment of token `base` (searchsorted-right; handles empty sequences).
    int s = 0;
    while (base >= s_cu[s + 1]) ++s;
    int lo = s_cu[s], hi = s_cu[s + 1];

    const int tmax = T - 1;

    // Window registers: rows base-2 .. base+2 (indices clamped; masks make
    // any clamped/garbage row harmless).
    float4 r0, r1, r2, r3, r4;
    {
        int j0 = base - 2 > 0 ? base - 2 : 0;
        int j1 = base - 1 > 0 ? base - 1 : 0;
        int j3 = base + 1 < tmax ? base + 1 : tmax;
        int j4 = base + 2 < tmax ? base + 2 : tmax;
        r0 = x4[(size_t)j0   * C4 + c4];
        r1 = x4[(size_t)j1   * C4 + c4];
        r2 = x4[(size_t)base * C4 + c4];
        r3 = x4[(size_t)j3   * C4 + c4];
        r4 = x4[(size_t)j4   * C4 + c4];
    }

    const int iend = base + len;                // <= T by construction
    int i = base;

    // Walking pointers: px -> row i+3 (next prefetch), po -> row i (output).
    const float4* px = x4 + (size_t)(i + 3) * C4 + c4;
    float4*       po = o4 + (size_t)i * C4 + c4;

    // ---- unroll-4 main loop: 4 independent prefetch loads per group ----
    for (; i + 3 < iend; i += 4) {
        // Prefetch rows i+3 .. i+6 (clamped at T-1; MLP=4).
        const float4* pc = px;
        const float4* plim = x4 + (size_t)tmax * C4 + c4;
        float4 n0 = *(pc            <= plim ? pc            : plim);
        float4 n1 = *(pc + C4       <= plim ? pc + C4       : plim);
        float4 n2 = *(pc + 2 * C4   <= plim ? pc + 2 * C4   : plim);
        float4 n3 = *(pc + 3 * C4   <= plim ? pc + 3 * C4   : plim);

        // Catch segment window up to token i (warp-uniform).
        while (i >= hi) { ++s; lo = s_cu[s]; hi = s_cu[s + 1]; }

        if (i - 2 >= lo && i + 5 < hi) {
            TOKEN_FAST(po         , r0, r1, r2, r3, r4);
            TOKEN_FAST(po + C4    , r1, r2, r3, r4, n0);
            TOKEN_FAST(po + 2 * C4, r2, r3, r4, n0, n1);
            TOKEN_FAST(po + 3 * C4, r3, r4, n0, n1, n2);
        } else {
            int ss = s, llo = lo, hhi = hi;
            TOKEN_SLOW(i    , po         , r0, r1, r2, r3, r4);
            TOKEN_SLOW(i + 1, po + C4    , r1, r2, r3, r4, n0);
            TOKEN_SLOW(i + 2, po + 2 * C4, r2, r3, r4, n0, n1);
            TOKEN_SLOW(i + 3, po + 3 * C4, r3, r4, n0, n1, n2);
        }

        // Shift window to rows i+2 .. i+6.
        r0 = r4; r1 = n0; r2 = n1; r3 = n2; r4 = n3;
        px += 4 * C4;
        po += 4 * C4;
    }

    // ---- scalar tail (<= 3 tokens) ----
    for (; i < iend; ++i) {
        while (i >= hi) { ++s; lo = s_cu[s]; hi = s_cu[s + 1]; }
        int ss = s, llo = lo, hhi = hi;
        TOKEN_SLOW(i, po, r0, r1, r2, r3, r4);
        int jn = i + 3 < tmax ? i + 3 : tmax;
        float4 nn = x4[(size_t)jn * C4 + c4];
        r0 = r1; r1 = r2; r2 = r3; r3 = r4; r4 = nn;
        po += C4;
    }
}

extern "C" void kernel_launch(void* const* d_in, const int* in_sizes, int n_in,
                              void* d_out, int out_size)
{
    const float* x      = (const float*)d_in[0];
    const int*   cu     = (const int*)  d_in[1];
    const float* weight = (const float*)d_in[2];
    const float* bias   = (const float*)d_in[3];
    float*       out    = (float*)d_out;

    const int T   = in_sizes[0] / CCH;
    const int ncu = in_sizes[1];

    dim3 block(C4, YR);                                      // (192, 2) = 384 threads
    canon_kernel<<<GRID, block>>>(x, cu, ncu, weight, bias, out, T);
}